// round 10
// baseline (speedup 1.0000x reference)
#include <cuda_runtime.h>
#include <cuda.h>
#include <math.h>
#include <stdint.h>

#define BATCH 16
#define SEQ   2048
#define DIM   128
#define MTOT  (BATCH * SEQ)

// ---------------- scratch (allocation-free device globals) ----------------
__device__ float g_h[MTOT * DIM];
__device__ float g_a[MTOT * DIM];

__device__ __forceinline__ float sigmoidf_(float v) {
    return 1.0f / (1.0f + __expf(-v));
}
__device__ __forceinline__ uint32_t smem_u32(const void* p) {
    uint32_t a;
    asm("{ .reg .u64 t; cvta.to.shared.u64 t, %1; cvt.u32.u64 %0, t; }" : "=r"(a) : "l"(p));
    return a;
}
// truncation split: hi = top tf32 bits, lo = exact remainder (2 ops).
__device__ __forceinline__ void tsplit(float x, uint32_t& hi, uint32_t& lo) {
    hi = __float_as_uint(x) & 0xFFFFE000u;
    lo = __float_as_uint(x - __uint_as_float(hi));
}
__device__ __forceinline__ void mma_tf32(float* d, const uint32_t* a,
                                         uint32_t b0, uint32_t b1) {
    asm volatile("mma.sync.aligned.m16n8k8.row.col.f32.tf32.tf32.f32 "
                 "{%0,%1,%2,%3}, {%4,%5,%6,%7}, {%8,%9}, {%0,%1,%2,%3};"
                 : "+f"(d[0]), "+f"(d[1]), "+f"(d[2]), "+f"(d[3])
                 : "r"(a[0]), "r"(a[1]), "r"(a[2]), "r"(a[3]), "r"(b0), "r"(b1));
}
// ---- TMA + mbarrier ----
__device__ __forceinline__ void tma2d(uint32_t dst, const void* map,
                                      int c0, int c1, uint32_t mbar) {
    asm volatile("cp.async.bulk.tensor.2d.shared::cta.global.tile.mbarrier::complete_tx::bytes "
                 "[%0], [%1, {%2, %3}], [%4];"
                 :: "r"(dst), "l"(map), "r"(c0), "r"(c1), "r"(mbar) : "memory");
}
__device__ __forceinline__ void tma3d(uint32_t dst, const void* map,
                                      int c0, int c1, int c2, uint32_t mbar) {
    asm volatile("cp.async.bulk.tensor.3d.shared::cta.global.tile.mbarrier::complete_tx::bytes "
                 "[%0], [%1, {%2, %3, %4}], [%5];"
                 :: "r"(dst), "l"(map), "r"(c0), "r"(c1), "r"(c2), "r"(mbar) : "memory");
}
__device__ __forceinline__ void mbar_init(uint32_t mbar, uint32_t cnt) {
    asm volatile("mbarrier.init.shared.b64 [%0], %1;" :: "r"(mbar), "r"(cnt) : "memory");
}
__device__ __forceinline__ void mbar_expect(uint32_t mbar, uint32_t bytes) {
    asm volatile("mbarrier.arrive.expect_tx.shared.b64 _, [%0], %1;"
                 :: "r"(mbar), "r"(bytes) : "memory");
}
__device__ __forceinline__ void mbar_wait(uint32_t mbar, uint32_t parity) {
    uint32_t done;
    asm volatile("{\n\t.reg .pred p;\n\t"
                 "mbarrier.try_wait.parity.acquire.cta.shared::cta.b64 p, [%1], %2;\n\t"
                 "selp.b32 %0, 1, 0, p;\n\t}"
                 : "=r"(done) : "r"(mbar), "r"(parity) : "memory");
    while (!done) {
        asm volatile("{\n\t.reg .pred p;\n\t"
                     "mbarrier.try_wait.parity.acquire.cta.shared::cta.b64 p, [%1], %2;\n\t"
                     "selp.b32 %0, 1, 0, p;\n\t}"
                     : "=r"(done) : "r"(mbar), "r"(parity) : "memory");
    }
}

// ===========================================================================
// Kernel 1: encode / spmm (UNCHANGED — proven 260us spmm)
// ===========================================================================
#define NSTAGE     3
#define STAGE_B    32768u
#define DATA_OFF   1024u
#define SMEM_BYTES (DATA_OFF + NSTAGE * STAGE_B)

template<int MODE, bool SPMM, int K>
__global__ void __launch_bounds__(256, 2)
gemm_tma(const __grid_constant__ CUtensorMap mA1,
         const __grid_constant__ CUtensorMap mB1,
         const float* __restrict__ bias1,
         const float* __restrict__ ffd, float* __restrict__ Cout)
{
    extern __shared__ __align__(1024) char smem[];
    const uint32_t sb = smem_u32(smem);

    const int tid = threadIdx.x, lane = tid & 31, warp = tid >> 5;
    const int wm = warp & 3, wn = warp >> 2;
    const int mbase = wm * 32, nbase = wn * 64;
    const int lq = lane >> 2, lt = lane & 3;

    const size_t rowTile = SPMM ? ((size_t)blockIdx.y * SEQ + (size_t)blockIdx.x * 128)
                                : ((size_t)blockIdx.x * 128);
    constexpr int NC = K / 32;

    if (tid == 0) {
#pragma unroll
        for (int s = 0; s < NSTAGE; s++) mbar_init(sb + s * 8, 1);
    }
    __syncthreads();

    auto issue = [&](int c) {
        const int s = c % NSTAGE;
        const uint32_t bar  = sb + s * 8;
        const uint32_t dstA = sb + DATA_OFF + s * STAGE_B;
        const uint32_t dstB = dstA + 16384u;
        const int k0 = c * 32;
        mbar_expect(bar, STAGE_B);
        if (SPMM) tma3d(dstA, &mA1, k0, (int)(blockIdx.x * 128), (int)blockIdx.y, bar);
        else      tma2d(dstA, &mA1, k0, (int)(blockIdx.x * 128), bar);
        const int brow = SPMM ? (int)(blockIdx.y * SEQ + k0) : k0;
#pragma unroll
        for (int i = 0; i < 4; i++)
            tma2d(dstB + i * 4096u, &mB1, i * 32, brow, bar);
    };

    float acc[2][8][4];
#pragma unroll
    for (int mi = 0; mi < 2; mi++)
#pragma unroll
        for (int j = 0; j < 8; j++)
#pragma unroll
            for (int q = 0; q < 4; q++) acc[mi][j][q] = 0.0f;

    const uint32_t aswz = (uint32_t)lq << 4;
    uint32_t bcol0[8], bcol1[8];
#pragma unroll
    for (int j = 0; j < 8; j++) {
        const int n  = nbase + j * 8 + lq;
        const uint32_t nb = (uint32_t)((n & 31) * 4);
        bcol0[j] = ((uint32_t)(n >> 5)) * 4096u + (nb ^ ((uint32_t)lt << 4));
        bcol1[j] = ((uint32_t)(n >> 5)) * 4096u + (nb ^ (((uint32_t)(lt + 4)) << 4));
    }

    if (tid == 0) {
        issue(0);
        if (NC > 1) issue(1);
        if (NC > 2) issue(2);
    }

#pragma unroll 1
    for (int c = 0; c < NC; ++c) {
        const int s = c % NSTAGE;
        mbar_wait(sb + s * 8, (uint32_t)((c / NSTAGE) & 1));
        const char* As = smem + DATA_OFF + s * STAGE_B;
        const char* Bs = As + 16384;

#pragma unroll
        for (int kk = 0; kk < 32; kk += 8) {
            const int kt0 = kk + lt, kt1 = kt0 + 4;
            uint32_t ah[2][4], al[2][4];
#pragma unroll
            for (int mi = 0; mi < 2; mi++) {
                const int r0 = mbase + mi * 16 + lq, r1 = r0 + 8;
                const uint32_t c0 = ((uint32_t)(kt0 * 4)) ^ aswz;
                const uint32_t c1 = ((uint32_t)(kt1 * 4)) ^ aswz;
                tsplit(*(const float*)(As + r0 * 128 + c0), ah[mi][0], al[mi][0]);
                tsplit(*(const float*)(As + r1 * 128 + c0), ah[mi][1], al[mi][1]);
                tsplit(*(const float*)(As + r0 * 128 + c1), ah[mi][2], al[mi][2]);
                tsplit(*(const float*)(As + r1 * 128 + c1), ah[mi][3], al[mi][3]);
            }
#pragma unroll
            for (int j = 0; j < 8; j++) {
                uint32_t bh0, bl0, bh1, bl1;
                tsplit(*(const float*)(Bs + kt0 * 128 + bcol0[j]), bh0, bl0);
                tsplit(*(const float*)(Bs + kt1 * 128 + bcol1[j]), bh1, bl1);
#pragma unroll
                for (int mi = 0; mi < 2; mi++) {
                    mma_tf32(acc[mi][j], ah[mi], bh0, bh1);
                    mma_tf32(acc[mi][j], ah[mi], bl0, bl1);
                    mma_tf32(acc[mi][j], al[mi], bh0, bh1);
                }
            }
        }
        __syncthreads();
        if (c + NSTAGE < NC && tid == 0) issue(c + NSTAGE);
    }

#pragma unroll
    for (int mi = 0; mi < 2; mi++) {
        const int rA = mbase + mi * 16 + lq;
        const size_t gr0 = rowTile + rA, gr1 = gr0 + 8;
        float s0 = 1.0f, s1 = 1.0f;
        if (MODE == 4) { s0 += ffd[gr0]; s1 += ffd[gr1]; }
#pragma unroll
        for (int j = 0; j < 8; j++) {
            const int col = nbase + j * 8 + lt * 2;
            float o[4];
#pragma unroll
            for (int q = 0; q < 4; q++) {
                const int cc = col + (q & 1);
                float v = acc[mi][j][q];
                if (MODE == 0) v = fmaxf(v + bias1[cc], 0.0f);
                else           v = v * ((q < 2) ? s0 : s1);
                o[q] = v;
            }
            *(float2*)&Cout[gr0 * 128 + col] = make_float2(o[0], o[1]);
            *(float2*)&Cout[gr1 * 128 + col] = make_float2(o[2], o[3]);
        }
    }
}

// ===========================================================================
// Kernel 2: fused GRU gates v3. 128-row tile, 512 threads (16 warps 4Mx4N),
// 1 CTA/SM, 5-deep weight ring (latency hidden). Pass order unchanged:
//   Wz0(a),Wz1(h) -> z(regs); Wr0(a),Wr1(h) -> ro=r*h -> overwrite H
//   (double-barriered); Wh0(a),Wh1(ro) -> h' = relu(.+bh)*z + h_gmem*(1-z)
// smem: bars 1KB | A 64KB | H/RO 64KB | W ring 5x16KB = 209KB
// ===========================================================================
#define NW     5
#define G_A    1024u
#define G_H    (G_A + 65536u)
#define G_W    (G_H + 65536u)
#define G_SMEM (G_W + (uint32_t)NW * 16384u)    // 214016

__global__ void __launch_bounds__(512, 1)
fused_gate(const __grid_constant__ CUtensorMap mA,
           const __grid_constant__ CUtensorMap mH,
           const __grid_constant__ CUtensorMap mWz0,
           const __grid_constant__ CUtensorMap mWz1,
           const __grid_constant__ CUtensorMap mWr0,
           const __grid_constant__ CUtensorMap mWr1,
           const __grid_constant__ CUtensorMap mWh0,
           const __grid_constant__ CUtensorMap mWh1,
           const float* __restrict__ bz0, const float* __restrict__ bz1,
           const float* __restrict__ br0, const float* __restrict__ br1,
           const float* __restrict__ bh0, const float* __restrict__ bh1,
           const float* Hg, float* OutH)
{
    extern __shared__ __align__(1024) char smem[];
    const uint32_t sb = smem_u32(smem);

    const int tid = threadIdx.x, lane = tid & 31, warp = tid >> 5;
    const int wm = warp & 3, wn = warp >> 2;
    const int mbase = wm * 32, nbase = wn * 32;
    const int lq = lane >> 2, lt = lane & 3;
    const int row0 = (int)(blockIdx.x * 128);

    const CUtensorMap* wmaps[6] = {&mWz0, &mWz1, &mWr0, &mWr1, &mWh0, &mWh1};

    if (tid == 0) {
        mbar_init(sb + 0, 1);                       // a/h tiles
#pragma unroll
        for (int s = 0; s < NW; s++) mbar_init(sb + 8 + s * 8, 1);
    }
    __syncthreads();

    auto issueW = [&](int q) {
        const int p = q >> 2, c = q & 3, s = q % NW;
        const uint32_t bar = sb + 8 + (uint32_t)s * 8;
        const uint32_t dst = sb + G_W + (uint32_t)s * 16384u;
        mbar_expect(bar, 16384u);
#pragma unroll
        for (int i = 0; i < 4; i++)
            tma2d(dst + i * 4096u, wmaps[p], i * 32, c * 32, bar);
    };

    if (tid == 0) {
        mbar_expect(sb + 0, 131072u);
#pragma unroll
        for (int i = 0; i < 4; i++) {
            tma2d(sb + G_A + i * 16384u, &mA, i * 32, row0, sb + 0);
            tma2d(sb + G_H + i * 16384u, &mH, i * 32, row0, sb + 0);
        }
#pragma unroll
        for (int s = 0; s < NW; s++) issueW(s);
    }

    float acc[2][4][4], zreg[2][4][4];
#pragma unroll
    for (int mi = 0; mi < 2; mi++)
#pragma unroll
        for (int j = 0; j < 4; j++)
#pragma unroll
            for (int q = 0; q < 4; q++) acc[mi][j][q] = 0.0f;

    uint32_t bcol0[4], bcol1[4];
#pragma unroll
    for (int j = 0; j < 4; j++) {
        const int n = nbase + j * 8 + lq;
        const uint32_t nb = (uint32_t)((n & 31) * 4);
        bcol0[j] = ((uint32_t)(n >> 5)) * 4096u + (nb ^ ((uint32_t)lt << 4));
        bcol1[j] = ((uint32_t)(n >> 5)) * 4096u + (nb ^ (((uint32_t)(lt + 4)) << 4));
    }

    // byte offset of element (row r, col c) in a 128-row tile region
    auto toff = [&](uint32_t region, int r, int c) -> uint32_t {
        return region + (uint32_t)(c >> 5) * 16384u + (uint32_t)r * 128u
               + (((uint32_t)((c & 31) * 4)) ^ ((uint32_t)(r & 7) << 4));
    };

    mbar_wait(sb + 0, 0);   // a & h tiles resident

#pragma unroll 1
    for (int q = 0; q < 24; ++q) {
        const int p = q >> 2, c = q & 3;
        mbar_wait(sb + 8 + (uint32_t)(q % NW) * 8, (uint32_t)((q / NW) & 1));
        // A source: passes 1,3 use h; pass 5 uses ro (stored over H); else a
        const uint32_t Areg = (p == 1 || p == 3 || p == 5) ? G_H : G_A;
        const char* Wb = smem + G_W + (uint32_t)(q % NW) * 16384u;

#pragma unroll
        for (int kk = 0; kk < 32; kk += 8) {
            const int kt0 = kk + lt, kt1 = kt0 + 4;
            uint32_t ah[2][4], al[2][4];
#pragma unroll
            for (int mi = 0; mi < 2; mi++) {
                const int r0 = mbase + mi * 16 + lq, r1 = r0 + 8;
                tsplit(*(const float*)(smem + toff(Areg, r0, c * 32 + kt0)), ah[mi][0], al[mi][0]);
                tsplit(*(const float*)(smem + toff(Areg, r1, c * 32 + kt0)), ah[mi][1], al[mi][1]);
                tsplit(*(const float*)(smem + toff(Areg, r0, c * 32 + kt1)), ah[mi][2], al[mi][2]);
                tsplit(*(const float*)(smem + toff(Areg, r1, c * 32 + kt1)), ah[mi][3], al[mi][3]);
            }
#pragma unroll
            for (int j = 0; j < 4; j++) {
                uint32_t bh0, bl0, bh1, bl1;
                tsplit(*(const float*)(Wb + kt0 * 128 + bcol0[j]), bh0, bl0);
                tsplit(*(const float*)(Wb + kt1 * 128 + bcol1[j]), bh1, bl1);
#pragma unroll
                for (int mi = 0; mi < 2; mi++) {
                    mma_tf32(acc[mi][j], ah[mi], bh0, bh1);
                    mma_tf32(acc[mi][j], ah[mi], bl0, bl1);
                    mma_tf32(acc[mi][j], al[mi], bh0, bh1);
                }
            }
        }

        if (q == 7) {       // z = sigmoid(acc + bz); keep in regs; reset acc
#pragma unroll
            for (int mi = 0; mi < 2; mi++)
#pragma unroll
                for (int j = 0; j < 4; j++)
#pragma unroll
                    for (int qq = 0; qq < 4; qq++) {
                        const int cc = nbase + j * 8 + lt * 2 + (qq & 1);
                        zreg[mi][j][qq] = sigmoidf_(acc[mi][j][qq] + bz0[cc] + bz1[cc]);
                        acc[mi][j][qq] = 0.0f;
                    }
        }
        if (q == 15) {
            // compute ro into regs (H reads), barrier, then overwrite H;
            // the end-of-iteration barrier orders writes before pass-5 reads.
#pragma unroll
            for (int mi = 0; mi < 2; mi++) {
                const int r0 = mbase + mi * 16 + lq;
#pragma unroll
                for (int j = 0; j < 4; j++)
#pragma unroll
                    for (int qq = 0; qq < 4; qq++) {
                        const int cc = nbase + j * 8 + lt * 2 + (qq & 1);
                        const int rr = (qq < 2) ? r0 : r0 + 8;
                        const float rv = sigmoidf_(acc[mi][j][qq] + br0[cc] + br1[cc]);
                        const float hv = *(const float*)(smem + toff(G_H, rr, cc));
                        acc[mi][j][qq] = rv * hv;
                    }
            }
            __syncthreads();     // all warps done READING H
#pragma unroll
            for (int mi = 0; mi < 2; mi++) {
                const int r0 = mbase + mi * 16 + lq;
#pragma unroll
                for (int j = 0; j < 4; j++)
#pragma unroll
                    for (int qq = 0; qq < 4; qq++) {
                        const int cc = nbase + j * 8 + lt * 2 + (qq & 1);
                        const int rr = (qq < 2) ? r0 : r0 + 8;
                        *(float*)(smem + toff(G_H, rr, cc)) = acc[mi][j][qq];
                        acc[mi][j][qq] = 0.0f;
                    }
            }
        }
        __syncthreads();
        if (q + NW < 24 && tid == 0) issueW(q + NW);
    }

    // epilogue: h' = relu(acc + bh)*z + h_gmem*(1-z)
#pragma unroll
    for (int mi = 0; mi < 2; mi++) {
        const int r0 = mbase + mi * 16 + lq;
        const size_t gr0 = (size_t)row0 + r0, gr1 = gr0 + 8;
#pragma unroll
        for (int j = 0; j < 4; j++) {
            const int col = nbase + j * 8 + lt * 2;
            const float2 h0 = *(const float2*)&Hg[gr0 * 128 + col];
            const float2 h1 = *(const float2*)&Hg[gr1 * 128 + col];
            float o[4];
            const float hv[4] = {h0.x, h0.y, h1.x, h1.y};
#pragma unroll
            for (int qq = 0; qq < 4; qq++) {
                const int cc = col + (qq & 1);
                const float zv = zreg[mi][j][qq];
                o[qq] = fmaxf(acc[mi][j][qq] + bh0[cc] + bh1[cc], 0.0f) * zv
                        + hv[qq] * (1.0f - zv);
            }
            *(float2*)&OutH[gr0 * 128 + col] = make_float2(o[0], o[1]);
            *(float2*)&OutH[gr1 * 128 + col] = make_float2(o[2], o[3]);
        }
    }
}

// ---------------------------------------------------------------------------
// host side
// ---------------------------------------------------------------------------
typedef CUresult (*pfn_encode_t)(CUtensorMap*, CUtensorMapDataType, cuuint32_t,
                                 void*, const cuuint64_t*, const cuuint64_t*,
                                 const cuuint32_t*, const cuuint32_t*,
                                 CUtensorMapInterleave, CUtensorMapSwizzle,
                                 CUtensorMapL2promotion, CUtensorMapFloatOOBfill);
static pfn_encode_t enc_fn = nullptr;

static void map2d(CUtensorMap* m, const void* ptr, uint64_t d0, uint64_t d1,
                  uint32_t b0, uint32_t b1) {
    cuuint64_t dims[2]    = {d0, d1};
    cuuint64_t strides[1] = {d0 * 4};
    cuuint32_t box[2]     = {b0, b1};
    cuuint32_t es[2]      = {1, 1};
    enc_fn(m, CU_TENSOR_MAP_DATA_TYPE_FLOAT32, 2, (void*)ptr, dims, strides, box, es,
           CU_TENSOR_MAP_INTERLEAVE_NONE, CU_TENSOR_MAP_SWIZZLE_128B,
           CU_TENSOR_MAP_L2_PROMOTION_L2_128B, CU_TENSOR_MAP_FLOAT_OOB_FILL_NONE);
}
static void map3d_sup(CUtensorMap* m, const void* ptr) {
    cuuint64_t dims[3]    = {SEQ, SEQ, BATCH};
    cuuint64_t strides[2] = {(uint64_t)SEQ * 4, (uint64_t)SEQ * SEQ * 4};
    cuuint32_t box[3]     = {32, 128, 1};
    cuuint32_t es[3]      = {1, 1, 1};
    enc_fn(m, CU_TENSOR_MAP_DATA_TYPE_FLOAT32, 3, (void*)ptr, dims, strides, box, es,
           CU_TENSOR_MAP_INTERLEAVE_NONE, CU_TENSOR_MAP_SWIZZLE_128B,
           CU_TENSOR_MAP_L2_PROMOTION_L2_128B, CU_TENSOR_MAP_FLOAT_OOB_FILL_NONE);
}

extern "C" void kernel_launch(void* const* d_in, const int* in_sizes, int n_in,
                              void* d_out, int out_size)
{
    const float* x       = (const float*)d_in[0];
    const float* support = (const float*)d_in[1];
    const float* ffd     = (const float*)d_in[2];
    // d_in[3] = mask (unused by reference)
    const float* We  = (const float*)d_in[4];
    const float* be  = (const float*)d_in[5];
    const float* Wz0 = (const float*)d_in[6];
    const float* bz0 = (const float*)d_in[7];
    const float* Wz1 = (const float*)d_in[8];
    const float* bz1 = (const float*)d_in[9];
    const float* Wr0 = (const float*)d_in[10];
    const float* br0 = (const float*)d_in[11];
    const float* Wr1 = (const float*)d_in[12];
    const float* br1 = (const float*)d_in[13];
    const float* Wh0 = (const float*)d_in[14];
    const float* bh0 = (const float*)d_in[15];
    const float* Wh1 = (const float*)d_in[16];
    const float* bh1 = (const float*)d_in[17];

    float *h, *a;
    cudaGetSymbolAddress((void**)&h, g_h);
    cudaGetSymbolAddress((void**)&a, g_a);

    if (!enc_fn) {
        cudaDriverEntryPointQueryResult qr;
        cudaGetDriverEntryPoint("cuTensorMapEncodeTiled", (void**)&enc_fn,
                                cudaEnableDefault, &qr);
    }

    CUtensorMap m_sup, m_x, m_hB, m_a128, m_h128;
    CUtensorMap m_We, m_Wz0, m_Wz1, m_Wr0, m_Wr1, m_Wh0, m_Wh1;
    map3d_sup(&m_sup, support);
    map2d(&m_x,    x, DIM, MTOT, 32, 128);
    map2d(&m_hB,   h, DIM, MTOT, 32, 32);
    map2d(&m_a128, a, DIM, MTOT, 32, 128);
    map2d(&m_h128, h, DIM, MTOT, 32, 128);
    map2d(&m_We,  We,  DIM, DIM, 32, 32);
    map2d(&m_Wz0, Wz0, DIM, DIM, 32, 32);
    map2d(&m_Wz1, Wz1, DIM, DIM, 32, 32);
    map2d(&m_Wr0, Wr0, DIM, DIM, 32, 32);
    map2d(&m_Wr1, Wr1, DIM, DIM, 32, 32);
    map2d(&m_Wh0, Wh0, DIM, DIM, 32, 32);
    map2d(&m_Wh1, Wh1, DIM, DIM, 32, 32);

    cudaFuncSetAttribute(gemm_tma<0, false, 128>, cudaFuncAttributeMaxDynamicSharedMemorySize, SMEM_BYTES);
    cudaFuncSetAttribute(gemm_tma<4, true, 2048>, cudaFuncAttributeMaxDynamicSharedMemorySize, SMEM_BYTES);
    cudaFuncSetAttribute(fused_gate, cudaFuncAttributeMaxDynamicSharedMemorySize, G_SMEM);

    const dim3 grd_enc(MTOT / 128);            // 256
    const dim3 grd_spmm(SEQ / 128, BATCH);     // (16,16)
    const dim3 grd_fused(MTOT / 128);          // 256

    // h = relu(x @ We + be)
    gemm_tma<0, false, 128><<<grd_enc, 256, SMEM_BYTES>>>(m_x, m_We, be, nullptr, h);

    for (int t = 0; t < 2; ++t) {
        // a = (support @ h) * (1 + FFD)
        gemm_tma<4, true, 2048><<<grd_spmm, 256, SMEM_BYTES>>>(m_sup, m_hB, nullptr, ffd, a);
        // fused gates + GRU combine
        float* dst = (t == 1) ? (float*)d_out : h;
        fused_gate<<<grd_fused, 512, G_SMEM>>>(m_a128, m_h128,
                                               m_Wz0, m_Wz1, m_Wr0, m_Wr1, m_Wh0, m_Wh1,
                                               bz0, bz1, br0, br1, bh0, bh1, h, dst);
    }
}

// round 11
// speedup vs baseline: 1.0342x; 1.0342x over previous
#include <cuda_runtime.h>
#include <cuda.h>
#include <math.h>
#include <stdint.h>

#define BATCH 16
#define SEQ   2048
#define DIM   128
#define MTOT  (BATCH * SEQ)

// ---------------- scratch (allocation-free device globals) ----------------
__device__ float g_h[MTOT * DIM];
__device__ float g_a[MTOT * DIM];

__device__ __forceinline__ float sigmoidf_(float v) {
    return 1.0f / (1.0f + __expf(-v));
}
__device__ __forceinline__ uint32_t smem_u32(const void* p) {
    uint32_t a;
    asm("{ .reg .u64 t; cvta.to.shared.u64 t, %1; cvt.u32.u64 %0, t; }" : "=r"(a) : "l"(p));
    return a;
}
// truncation split: hi = top tf32 bits, lo = exact remainder (2 ops).
__device__ __forceinline__ void tsplit(float x, uint32_t& hi, uint32_t& lo) {
    hi = __float_as_uint(x) & 0xFFFFE000u;
    lo = __float_as_uint(x - __uint_as_float(hi));
}
__device__ __forceinline__ void mma_tf32(float* d, const uint32_t* a,
                                         uint32_t b0, uint32_t b1) {
    asm volatile("mma.sync.aligned.m16n8k8.row.col.f32.tf32.tf32.f32 "
                 "{%0,%1,%2,%3}, {%4,%5,%6,%7}, {%8,%9}, {%0,%1,%2,%3};"
                 : "+f"(d[0]), "+f"(d[1]), "+f"(d[2]), "+f"(d[3])
                 : "r"(a[0]), "r"(a[1]), "r"(a[2]), "r"(a[3]), "r"(b0), "r"(b1));
}
// ---- TMA + mbarrier ----
__device__ __forceinline__ void tma2d(uint32_t dst, const void* map,
                                      int c0, int c1, uint32_t mbar) {
    asm volatile("cp.async.bulk.tensor.2d.shared::cta.global.tile.mbarrier::complete_tx::bytes "
                 "[%0], [%1, {%2, %3}], [%4];"
                 :: "r"(dst), "l"(map), "r"(c0), "r"(c1), "r"(mbar) : "memory");
}
__device__ __forceinline__ void tma3d(uint32_t dst, const void* map,
                                      int c0, int c1, int c2, uint32_t mbar) {
    asm volatile("cp.async.bulk.tensor.3d.shared::cta.global.tile.mbarrier::complete_tx::bytes "
                 "[%0], [%1, {%2, %3, %4}], [%5];"
                 :: "r"(dst), "l"(map), "r"(c0), "r"(c1), "r"(c2), "r"(mbar) : "memory");
}
__device__ __forceinline__ void mbar_init(uint32_t mbar, uint32_t cnt) {
    asm volatile("mbarrier.init.shared.b64 [%0], %1;" :: "r"(mbar), "r"(cnt) : "memory");
}
__device__ __forceinline__ void mbar_expect(uint32_t mbar, uint32_t bytes) {
    asm volatile("mbarrier.arrive.expect_tx.shared.b64 _, [%0], %1;"
                 :: "r"(mbar), "r"(bytes) : "memory");
}
__device__ __forceinline__ void mbar_arrive(uint32_t mbar) {
    asm volatile("mbarrier.arrive.shared.b64 _, [%0];" :: "r"(mbar) : "memory");
}
__device__ __forceinline__ void mbar_wait(uint32_t mbar, uint32_t parity) {
    uint32_t done;
    asm volatile("{\n\t.reg .pred p;\n\t"
                 "mbarrier.try_wait.parity.acquire.cta.shared::cta.b64 p, [%1], %2;\n\t"
                 "selp.b32 %0, 1, 0, p;\n\t}"
                 : "=r"(done) : "r"(mbar), "r"(parity) : "memory");
    while (!done) {
        asm volatile("{\n\t.reg .pred p;\n\t"
                     "mbarrier.try_wait.parity.acquire.cta.shared::cta.b64 p, [%1], %2;\n\t"
                     "selp.b32 %0, 1, 0, p;\n\t}"
                     : "=r"(done) : "r"(mbar), "r"(parity) : "memory");
    }
}

// ===========================================================================
// Kernel 1: encode / spmm — v2: per-warp pipelined (NO per-chunk syncthreads).
// full[s] at sb+0/8/16 (tx barriers), empty[s] at sb+24/32/40 (8 arrivals).
// Consumers wait full only; warp0-lane0 waits empty[s] before reissuing s.
// ===========================================================================
#define NSTAGE     3
#define STAGE_B    32768u
#define DATA_OFF   1024u
#define SMEM_BYTES (DATA_OFF + NSTAGE * STAGE_B)

template<int MODE, bool SPMM, int K>
__global__ void __launch_bounds__(256, 2)
gemm_tma(const __grid_constant__ CUtensorMap mA1,
         const __grid_constant__ CUtensorMap mB1,
         const float* __restrict__ bias1,
         const float* __restrict__ ffd, float* __restrict__ Cout)
{
    extern __shared__ __align__(1024) char smem[];
    const uint32_t sb = smem_u32(smem);

    const int tid = threadIdx.x, lane = tid & 31, warp = tid >> 5;
    const int wm = warp & 3, wn = warp >> 2;
    const int mbase = wm * 32, nbase = wn * 64;
    const int lq = lane >> 2, lt = lane & 3;

    const size_t rowTile = SPMM ? ((size_t)blockIdx.y * SEQ + (size_t)blockIdx.x * 128)
                                : ((size_t)blockIdx.x * 128);
    constexpr int NC = K / 32;

    if (tid == 0) {
#pragma unroll
        for (int s = 0; s < NSTAGE; s++) {
            mbar_init(sb + s * 8, 1);           // full (tx)
            mbar_init(sb + 24 + s * 8, 8);      // empty (8 warps)
        }
    }
    __syncthreads();

    auto issue = [&](int c) {
        const int s = c % NSTAGE;
        const uint32_t bar  = sb + s * 8;
        const uint32_t dstA = sb + DATA_OFF + s * STAGE_B;
        const uint32_t dstB = dstA + 16384u;
        const int k0 = c * 32;
        mbar_expect(bar, STAGE_B);
        if (SPMM) tma3d(dstA, &mA1, k0, (int)(blockIdx.x * 128), (int)blockIdx.y, bar);
        else      tma2d(dstA, &mA1, k0, (int)(blockIdx.x * 128), bar);
        const int brow = SPMM ? (int)(blockIdx.y * SEQ + k0) : k0;
#pragma unroll
        for (int i = 0; i < 4; i++)
            tma2d(dstB + i * 4096u, &mB1, i * 32, brow, bar);
    };

    float acc[2][8][4];
#pragma unroll
    for (int mi = 0; mi < 2; mi++)
#pragma unroll
        for (int j = 0; j < 8; j++)
#pragma unroll
            for (int q = 0; q < 4; q++) acc[mi][j][q] = 0.0f;

    const uint32_t aswz = (uint32_t)lq << 4;
    uint32_t bcol0[8], bcol1[8];
#pragma unroll
    for (int j = 0; j < 8; j++) {
        const int n  = nbase + j * 8 + lq;
        const uint32_t nb = (uint32_t)((n & 31) * 4);
        bcol0[j] = ((uint32_t)(n >> 5)) * 4096u + (nb ^ ((uint32_t)lt << 4));
        bcol1[j] = ((uint32_t)(n >> 5)) * 4096u + (nb ^ (((uint32_t)(lt + 4)) << 4));
    }

    if (tid == 0) {
        issue(0);
        if (NC > 1) issue(1);
        if (NC > 2) issue(2);
    }

#pragma unroll 1
    for (int c = 0; c < NC; ++c) {
        const int s = c % NSTAGE;
        mbar_wait(sb + s * 8, (uint32_t)((c / NSTAGE) & 1));
        const char* As = smem + DATA_OFF + s * STAGE_B;
        const char* Bs = As + 16384;

#pragma unroll
        for (int kk = 0; kk < 32; kk += 8) {
            const int kt0 = kk + lt, kt1 = kt0 + 4;
            uint32_t ah[2][4], al[2][4];
#pragma unroll
            for (int mi = 0; mi < 2; mi++) {
                const int r0 = mbase + mi * 16 + lq, r1 = r0 + 8;
                const uint32_t c0 = ((uint32_t)(kt0 * 4)) ^ aswz;
                const uint32_t c1 = ((uint32_t)(kt1 * 4)) ^ aswz;
                tsplit(*(const float*)(As + r0 * 128 + c0), ah[mi][0], al[mi][0]);
                tsplit(*(const float*)(As + r1 * 128 + c0), ah[mi][1], al[mi][1]);
                tsplit(*(const float*)(As + r0 * 128 + c1), ah[mi][2], al[mi][2]);
                tsplit(*(const float*)(As + r1 * 128 + c1), ah[mi][3], al[mi][3]);
            }
#pragma unroll
            for (int j = 0; j < 8; j++) {
                uint32_t bh0, bl0, bh1, bl1;
                tsplit(*(const float*)(Bs + kt0 * 128 + bcol0[j]), bh0, bl0);
                tsplit(*(const float*)(Bs + kt1 * 128 + bcol1[j]), bh1, bl1);
#pragma unroll
                for (int mi = 0; mi < 2; mi++) {
                    mma_tf32(acc[mi][j], ah[mi], bh0, bh1);
                    mma_tf32(acc[mi][j], ah[mi], bl0, bl1);
                    mma_tf32(acc[mi][j], al[mi], bh0, bh1);
                }
            }
        }
        // warp done consuming stage s (HMMA issue implies LDS of this stage drained)
        if (lane == 0) mbar_arrive(sb + 24 + s * 8);
        // producer: reissue stage s for chunk c+3 once all 8 warps arrived
        if (tid == 0 && c + NSTAGE < NC) {
            mbar_wait(sb + 24 + s * 8, (uint32_t)((c / NSTAGE) & 1));
            issue(c + NSTAGE);
        }
    }

#pragma unroll
    for (int mi = 0; mi < 2; mi++) {
        const int rA = mbase + mi * 16 + lq;
        const size_t gr0 = rowTile + rA, gr1 = gr0 + 8;
        float s0 = 1.0f, s1 = 1.0f;
        if (MODE == 4) { s0 += ffd[gr0]; s1 += ffd[gr1]; }
#pragma unroll
        for (int j = 0; j < 8; j++) {
            const int col = nbase + j * 8 + lt * 2;
            float o[4];
#pragma unroll
            for (int q = 0; q < 4; q++) {
                const int cc = col + (q & 1);
                float v = acc[mi][j][q];
                if (MODE == 0) v = fmaxf(v + bias1[cc], 0.0f);
                else           v = v * ((q < 2) ? s0 : s1);
                o[q] = v;
            }
            *(float2*)&Cout[gr0 * 128 + col] = make_float2(o[0], o[1]);
            *(float2*)&Cout[gr1 * 128 + col] = make_float2(o[2], o[3]);
        }
    }
}

// ===========================================================================
// Kernel 2: fused GRU gates v2.1 (REVERTED to round-9 best: 64-row tile,
// 256 threads, 2 CTAs/SM, race-fixed double barrier at q==15).
// ===========================================================================
#define G_A    1024u
#define G_H    (G_A + 32768u)
#define G_W    (G_H + 32768u)
#define G_SMEM (G_W + 2u * 16384u)    // 99328

__global__ void __launch_bounds__(256, 2)
fused_gate(const __grid_constant__ CUtensorMap mA,
           const __grid_constant__ CUtensorMap mH,
           const __grid_constant__ CUtensorMap mWz0,
           const __grid_constant__ CUtensorMap mWz1,
           const __grid_constant__ CUtensorMap mWr0,
           const __grid_constant__ CUtensorMap mWr1,
           const __grid_constant__ CUtensorMap mWh0,
           const __grid_constant__ CUtensorMap mWh1,
           const float* __restrict__ bz0, const float* __restrict__ bz1,
           const float* __restrict__ br0, const float* __restrict__ br1,
           const float* __restrict__ bh0, const float* __restrict__ bh1,
           const float* Hg, float* OutH)
{
    extern __shared__ __align__(1024) char smem[];
    const uint32_t sb = smem_u32(smem);

    const int tid = threadIdx.x, lane = tid & 31, warp = tid >> 5;
    const int wm = warp & 1, wn = warp >> 1;
    const int mbase = wm * 32, nbase = wn * 32;
    const int lq = lane >> 2, lt = lane & 3;
    const int row0 = (int)(blockIdx.x * 64);

    const CUtensorMap* wmaps[6] = {&mWz0, &mWz1, &mWr0, &mWr1, &mWh0, &mWh1};

    if (tid == 0) {
        mbar_init(sb + 0, 1);
        mbar_init(sb + 8, 1);
        mbar_init(sb + 16, 1);
    }
    __syncthreads();

    auto issueW = [&](int q) {
        const int p = q >> 2, c = q & 3;
        const uint32_t bar = sb + (uint32_t)(q & 1) * 8;
        const uint32_t dst = sb + G_W + (uint32_t)(q & 1) * 16384u;
        mbar_expect(bar, 16384u);
#pragma unroll
        for (int i = 0; i < 4; i++)
            tma2d(dst + i * 4096u, wmaps[p], i * 32, c * 32, bar);
    };

    if (tid == 0) {
        mbar_expect(sb + 16, 65536u);
#pragma unroll
        for (int i = 0; i < 4; i++) {
            tma2d(sb + G_A + i * 8192u, &mA, i * 32, row0, sb + 16);
            tma2d(sb + G_H + i * 8192u, &mH, i * 32, row0, sb + 16);
        }
        issueW(0);
        issueW(1);
    }

    float acc[2][4][4], zreg[2][4][4];
#pragma unroll
    for (int mi = 0; mi < 2; mi++)
#pragma unroll
        for (int j = 0; j < 4; j++)
#pragma unroll
            for (int q = 0; q < 4; q++) acc[mi][j][q] = 0.0f;

    uint32_t bcol0[4], bcol1[4];
#pragma unroll
    for (int j = 0; j < 4; j++) {
        const int n = nbase + j * 8 + lq;
        const uint32_t nb = (uint32_t)((n & 31) * 4);
        bcol0[j] = ((uint32_t)(n >> 5)) * 4096u + (nb ^ ((uint32_t)lt << 4));
        bcol1[j] = ((uint32_t)(n >> 5)) * 4096u + (nb ^ (((uint32_t)(lt + 4)) << 4));
    }

    // byte offset (from smem base) of element (row r, col c) in a 64-row tile
    auto toff = [&](uint32_t region, int r, int c) -> uint32_t {
        return region + (uint32_t)(c >> 5) * 8192u + (uint32_t)r * 128u
               + (((uint32_t)((c & 31) * 4)) ^ ((uint32_t)(r & 7) << 4));
    };

    mbar_wait(sb + 16, 0);   // a & h tiles resident

#pragma unroll 1
    for (int q = 0; q < 24; ++q) {
        const int p = q >> 2, c = q & 3;
        mbar_wait(sb + (uint32_t)(q & 1) * 8, (uint32_t)((q >> 1) & 1));
        // A source: passes 1,3 use h; pass 5 uses ro (stored over H); else a
        const uint32_t Areg = (p == 1 || p == 3 || p == 5) ? G_H : G_A;
        const char* Wb = smem + G_W + (uint32_t)(q & 1) * 16384u;

#pragma unroll
        for (int kk = 0; kk < 32; kk += 8) {
            const int kt0 = kk + lt, kt1 = kt0 + 4;
            uint32_t ah[2][4], al[2][4];
#pragma unroll
            for (int mi = 0; mi < 2; mi++) {
                const int r0 = mbase + mi * 16 + lq, r1 = r0 + 8;
                tsplit(*(const float*)(smem + toff(Areg, r0, c * 32 + kt0)), ah[mi][0], al[mi][0]);
                tsplit(*(const float*)(smem + toff(Areg, r1, c * 32 + kt0)), ah[mi][1], al[mi][1]);
                tsplit(*(const float*)(smem + toff(Areg, r0, c * 32 + kt1)), ah[mi][2], al[mi][2]);
                tsplit(*(const float*)(smem + toff(Areg, r1, c * 32 + kt1)), ah[mi][3], al[mi][3]);
            }
#pragma unroll
            for (int j = 0; j < 4; j++) {
                uint32_t bh0, bl0, bh1, bl1;
                tsplit(*(const float*)(Wb + kt0 * 128 + bcol0[j]), bh0, bl0);
                tsplit(*(const float*)(Wb + kt1 * 128 + bcol1[j]), bh1, bl1);
#pragma unroll
                for (int mi = 0; mi < 2; mi++) {
                    mma_tf32(acc[mi][j], ah[mi], bh0, bh1);
                    mma_tf32(acc[mi][j], ah[mi], bl0, bl1);
                    mma_tf32(acc[mi][j], al[mi], bh0, bh1);
                }
            }
        }

        if (q == 7) {       // z = sigmoid(acc + bz); keep in regs; reset acc
#pragma unroll
            for (int mi = 0; mi < 2; mi++)
#pragma unroll
                for (int j = 0; j < 4; j++)
#pragma unroll
                    for (int qq = 0; qq < 4; qq++) {
                        const int cc = nbase + j * 8 + lt * 2 + (qq & 1);
                        zreg[mi][j][qq] = sigmoidf_(acc[mi][j][qq] + bz0[cc] + bz1[cc]);
                        acc[mi][j][qq] = 0.0f;
                    }
        }
        if (q == 15) {
            // compute ro into regs (H reads), barrier so all warps finish
            // reading H, then overwrite H; end-of-iteration barrier orders
            // the writes before pass-5 reads.
#pragma unroll
            for (int mi = 0; mi < 2; mi++) {
                const int r0 = mbase + mi * 16 + lq;
#pragma unroll
                for (int j = 0; j < 4; j++)
#pragma unroll
                    for (int qq = 0; qq < 4; qq++) {
                        const int cc = nbase + j * 8 + lt * 2 + (qq & 1);
                        const int rr = (qq < 2) ? r0 : r0 + 8;
                        const float rv = sigmoidf_(acc[mi][j][qq] + br0[cc] + br1[cc]);
                        const float hv = *(const float*)(smem + toff(G_H, rr, cc));
                        acc[mi][j][qq] = rv * hv;
                    }
            }
            __syncthreads();     // all warps done READING H
#pragma unroll
            for (int mi = 0; mi < 2; mi++) {
                const int r0 = mbase + mi * 16 + lq;
#pragma unroll
                for (int j = 0; j < 4; j++)
#pragma unroll
                    for (int qq = 0; qq < 4; qq++) {
                        const int cc = nbase + j * 8 + lt * 2 + (qq & 1);
                        const int rr = (qq < 2) ? r0 : r0 + 8;
                        *(float*)(smem + toff(G_H, rr, cc)) = acc[mi][j][qq];
                        acc[mi][j][qq] = 0.0f;
                    }
            }
        }
        __syncthreads();
        if (q + 2 < 24 && tid == 0) issueW(q + 2);
    }

    // epilogue: h' = relu(acc + bh)*z + h_gmem*(1-z)
#pragma unroll
    for (int mi = 0; mi < 2; mi++) {
        const int r0 = mbase + mi * 16 + lq;
        const size_t gr0 = (size_t)row0 + r0, gr1 = gr0 + 8;
#pragma unroll
        for (int j = 0; j < 4; j++) {
            const int col = nbase + j * 8 + lt * 2;
            const float2 h0 = *(const float2*)&Hg[gr0 * 128 + col];
            const float2 h1 = *(const float2*)&Hg[gr1 * 128 + col];
            float o[4];
            const float hv[4] = {h0.x, h0.y, h1.x, h1.y};
#pragma unroll
            for (int qq = 0; qq < 4; qq++) {
                const int cc = col + (qq & 1);
                const float zv = zreg[mi][j][qq];
                o[qq] = fmaxf(acc[mi][j][qq] + bh0[cc] + bh1[cc], 0.0f) * zv
                        + hv[qq] * (1.0f - zv);
            }
            *(float2*)&OutH[gr0 * 128 + col] = make_float2(o[0], o[1]);
            *(float2*)&OutH[gr1 * 128 + col] = make_float2(o[2], o[3]);
        }
    }
}

// ---------------------------------------------------------------------------
// host side
// ---------------------------------------------------------------------------
typedef CUresult (*pfn_encode_t)(CUtensorMap*, CUtensorMapDataType, cuuint32_t,
                                 void*, const cuuint64_t*, const cuuint64_t*,
                                 const cuuint32_t*, const cuuint32_t*,
                                 CUtensorMapInterleave, CUtensorMapSwizzle,
                                 CUtensorMapL2promotion, CUtensorMapFloatOOBfill);
static pfn_encode_t enc_fn = nullptr;

static void map2d(CUtensorMap* m, const void* ptr, uint64_t d0, uint64_t d1,
                  uint32_t b0, uint32_t b1) {
    cuuint64_t dims[2]    = {d0, d1};
    cuuint64_t strides[1] = {d0 * 4};
    cuuint32_t box[2]     = {b0, b1};
    cuuint32_t es[2]      = {1, 1};
    enc_fn(m, CU_TENSOR_MAP_DATA_TYPE_FLOAT32, 2, (void*)ptr, dims, strides, box, es,
           CU_TENSOR_MAP_INTERLEAVE_NONE, CU_TENSOR_MAP_SWIZZLE_128B,
           CU_TENSOR_MAP_L2_PROMOTION_L2_128B, CU_TENSOR_MAP_FLOAT_OOB_FILL_NONE);
}
static void map3d_sup(CUtensorMap* m, const void* ptr) {
    cuuint64_t dims[3]    = {SEQ, SEQ, BATCH};
    cuuint64_t strides[2] = {(uint64_t)SEQ * 4, (uint64_t)SEQ * SEQ * 4};
    cuuint32_t box[3]     = {32, 128, 1};
    cuuint32_t es[3]      = {1, 1, 1};
    enc_fn(m, CU_TENSOR_MAP_DATA_TYPE_FLOAT32, 3, (void*)ptr, dims, strides, box, es,
           CU_TENSOR_MAP_INTERLEAVE_NONE, CU_TENSOR_MAP_SWIZZLE_128B,
           CU_TENSOR_MAP_L2_PROMOTION_L2_128B, CU_TENSOR_MAP_FLOAT_OOB_FILL_NONE);
}

extern "C" void kernel_launch(void* const* d_in, const int* in_sizes, int n_in,
                              void* d_out, int out_size)
{
    const float* x       = (const float*)d_in[0];
    const float* support = (const float*)d_in[1];
    const float* ffd     = (const float*)d_in[2];
    // d_in[3] = mask (unused by reference)
    const float* We  = (const float*)d_in[4];
    const float* be  = (const float*)d_in[5];
    const float* Wz0 = (const float*)d_in[6];
    const float* bz0 = (const float*)d_in[7];
    const float* Wz1 = (const float*)d_in[8];
    const float* bz1 = (const float*)d_in[9];
    const float* Wr0 = (const float*)d_in[10];
    const float* br0 = (const float*)d_in[11];
    const float* Wr1 = (const float*)d_in[12];
    const float* br1 = (const float*)d_in[13];
    const float* Wh0 = (const float*)d_in[14];
    const float* bh0 = (const float*)d_in[15];
    const float* Wh1 = (const float*)d_in[16];
    const float* bh1 = (const float*)d_in[17];

    float *h, *a;
    cudaGetSymbolAddress((void**)&h, g_h);
    cudaGetSymbolAddress((void**)&a, g_a);

    if (!enc_fn) {
        cudaDriverEntryPointQueryResult qr;
        cudaGetDriverEntryPoint("cuTensorMapEncodeTiled", (void**)&enc_fn,
                                cudaEnableDefault, &qr);
    }

    CUtensorMap m_sup, m_x, m_hB, m_a64, m_h64;
    CUtensorMap m_We, m_Wz0, m_Wz1, m_Wr0, m_Wr1, m_Wh0, m_Wh1;
    map3d_sup(&m_sup, support);
    map2d(&m_x,   x, DIM, MTOT, 32, 128);
    map2d(&m_hB,  h, DIM, MTOT, 32, 32);
    map2d(&m_a64, a, DIM, MTOT, 32, 64);
    map2d(&m_h64, h, DIM, MTOT, 32, 64);
    map2d(&m_We,  We,  DIM, DIM, 32, 32);
    map2d(&m_Wz0, Wz0, DIM, DIM, 32, 32);
    map2d(&m_Wz1, Wz1, DIM, DIM, 32, 32);
    map2d(&m_Wr0, Wr0, DIM, DIM, 32, 32);
    map2d(&m_Wr1, Wr1, DIM, DIM, 32, 32);
    map2d(&m_Wh0, Wh0, DIM, DIM, 32, 32);
    map2d(&m_Wh1, Wh1, DIM, DIM, 32, 32);

    cudaFuncSetAttribute(gemm_tma<0, false, 128>, cudaFuncAttributeMaxDynamicSharedMemorySize, SMEM_BYTES);
    cudaFuncSetAttribute(gemm_tma<4, true, 2048>, cudaFuncAttributeMaxDynamicSharedMemorySize, SMEM_BYTES);
    cudaFuncSetAttribute(fused_gate, cudaFuncAttributeMaxDynamicSharedMemorySize, G_SMEM);

    const dim3 grd_enc(MTOT / 128);            // 256
    const dim3 grd_spmm(SEQ / 128, BATCH);     // (16,16)
    const dim3 grd_fused(MTOT / 64);           // 512

    // h = relu(x @ We + be)
    gemm_tma<0, false, 128><<<grd_enc, 256, SMEM_BYTES>>>(m_x, m_We, be, nullptr, h);

    for (int t = 0; t < 2; ++t) {
        // a = (support @ h) * (1 + FFD)
        gemm_tma<4, true, 2048><<<grd_spmm, 256, SMEM_BYTES>>>(m_sup, m_hB, nullptr, ffd, a);
        // fused gates + GRU combine
        float* dst = (t == 1) ? (float*)d_out : h;
        fused_gate<<<grd_fused, 256, G_SMEM>>>(m_a64, m_h64,
                                               m_Wz0, m_Wz1, m_Wr0, m_Wr1, m_Wh0, m_Wh1,
                                               bz0, bz1, br0, br1, bh0, bh1, h, dst);
    }
}